// round 4
// baseline (speedup 1.0000x reference)
#include <cuda_runtime.h>
#include <math.h>

// x, x_r: (1, 3, 32, 512, 512) float32
// patch hc=wc=32 -> 16x16 patches/frame, 32 frames; patch = 3*32*32 = 3072 elems
// P = mean(|x-x_r|*0.5) per patch ; out = log( mean_t( max(0, max_p P) ) )
//
// Grid: 1024 CTAs = (t:32) x (ph:16) x (half:2), 256 threads.
// Each CTA: 3ch x 32 rows x 256 cols = 6144 float4 per tensor (24 f4/thread),
// covering 8 patches. One resident wave (8 CTAs/SM x 148 = 1184 >= 1024).

#define C_STRIDE4  (32 * 512 * 512 / 4)   // channel stride in float4
#define T_STRIDE4  (512 * 512 / 4)        // frame stride in float4
#define W4         128                    // row stride in float4
#define NCTA       1024
#define NFRAME     32

__device__ int          g_M[NFRAME];   // per-frame max (float bits, all >= 0); 0-init = clamp(0)
__device__ unsigned int g_count;

__global__ __launch_bounds__(256) void patch_loss_fused(
    const float4* __restrict__ x, const float4* __restrict__ xr,
    float* __restrict__ out)
{
    const int b    = blockIdx.x;          // 0..1023
    const int t    = b >> 5;              // frame
    const int ph   = (b >> 1) & 15;       // patch row block
    const int half = b & 1;               // which 256-col half
    const int tid  = threadIdx.x;

    const int base4 = t * T_STRIDE4 + (ph * 32) * W4 + half * 64;

    // tid+256k keeps col = tid&63 invariant -> thread stays in one patch column pw
    float a0 = 0.f, a1 = 0.f, a2 = 0.f, a3 = 0.f;
    #pragma unroll
    for (int k = 0; k < 24; k++) {
        const int j   = tid + (k << 8);      // 0..6143 float4 index in CTA tile
        const int c   = j >> 11;             // channel (32 rows x 64 cols = 2048 f4)
        const int rem = j & 2047;
        const int r   = rem >> 6;            // row in patch block
        const int col = rem & 63;            // float4 col within half
        const int idx = base4 + c * C_STRIDE4 + r * W4 + col;
        float4 a = __ldcs(&x[idx]);
        float4 v = __ldcs(&xr[idx]);
        float s = fabsf(a.x - v.x) + fabsf(a.y - v.y)
                + fabsf(a.z - v.z) + fabsf(a.w - v.w);
        if      ((k & 3) == 0) a0 += s;
        else if ((k & 3) == 1) a1 += s;
        else if ((k & 3) == 2) a2 += s;
        else                   a3 += s;
    }
    float acc = (a0 + a1) + (a2 + a3);

    // 8-lane segmented reduce: lanes with lane%8==0 hold their patch-column partial
    #pragma unroll
    for (int o = 4; o > 0; o >>= 1)
        acc += __shfl_down_sync(0xFFFFFFFFu, acc, o);

    // warp w covers pw = (w&1)*4 + lane/8, replicate rep = w>>2... (w>>1: 4 reps)
    __shared__ float s_p[8][4];
    __shared__ bool  last;
    {
        const int w    = tid >> 5;
        const int lane = tid & 31;
        if ((lane & 7) == 0) {
            const int pw  = ((w & 1) << 2) + (lane >> 3);  // 0..7 (local patch in half)
            const int rep = w >> 1;                        // 0..3
            s_p[pw][rep] = acc;
        }
    }
    __syncthreads();

    if (tid < 8) {
        const float P = (s_p[tid][0] + s_p[tid][1] + s_p[tid][2] + s_p[tid][3])
                        * (0.5f / 3072.0f);
        float m = P;
        #pragma unroll
        for (int o = 4; o > 0; o >>= 1)
            m = fmaxf(m, __shfl_down_sync(0xFFu, m, o));
        if (tid == 0) {
            atomicMax(&g_M[t], __float_as_int(m));   // valid: m >= 0
            __threadfence();
            const unsigned int old = atomicAdd(&g_count, 1u);
            last = (old == NCTA - 1);
        }
    }
    __syncthreads();

    if (last) {
        __threadfence();
        if (tid < 32) {
            float v = __int_as_float(__ldcg(&g_M[tid]));
            #pragma unroll
            for (int o = 16; o > 0; o >>= 1)
                v += __shfl_down_sync(0xFFFFFFFFu, v, o);
            if (tid == 0) {
                out[0] = logf(v * (1.0f / 32.0f));
                g_count = 0;               // reset for next graph replay
            }
            g_M[tid] = 0;
        }
    }
}

extern "C" void kernel_launch(void* const* d_in, const int* in_sizes, int n_in,
                              void* d_out, int out_size)
{
    const float4* x  = (const float4*)d_in[0];
    const float4* xr = (const float4*)d_in[1];
    patch_loss_fused<<<NCTA, 256>>>(x, xr, (float*)d_out);
}

// round 6
// speedup vs baseline: 1.1750x; 1.1750x over previous
#include <cuda_runtime.h>
#include <math.h>

// x, x_r: (1, 3, 32, 512, 512) float32
// patch: hc=wc=32 -> 16x16 patches/frame, 32 frames -> 8192 patches of 3*32*32=3072 elems
// P = mean(|x - x_r| * 0.5) per patch ; out = log( mean_t( max(0, max_p P) ) )
//
// Persistent grid: 1184 CTAs (148 SM x 8), 256 threads, grid-stride over 8192 patches.
// Per patch: 768 float4 per tensor -> 3 f4/thread/tensor (6 LDG.128 in flight).

#define C_STRIDE4  (32 * 512 * 512 / 4)
#define T_STRIDE4  (512 * 512 / 4)
#define W4         128
#define NPATCH     8192
#define NFRAME     32
#define NCTA       1184                 // 148 SMs x 8 CTAs/SM -> single resident wave

__device__ int          g_M[NFRAME];   // per-frame max (float bits, all >= 0); 0-init = clamp(0)
__device__ unsigned int g_count;       // CTA completion counter

__global__ __launch_bounds__(256, 8) void patch_loss_fused(
    const float4* __restrict__ x, const float4* __restrict__ xr,
    float* __restrict__ out)
{
    const int tid = threadIdx.x;
    __shared__ float s[8];
    __shared__ bool  last;

    for (int p = blockIdx.x; p < NPATCH; p += NCTA) {
        const int t  = p >> 8;              // frame
        const int ph = (p >> 4) & 15;       // patch row
        const int pw = p & 15;              // patch col

        const int base4 = t * T_STRIDE4 + (ph * 32) * W4 + pw * 8;

        float acc = 0.0f;
        #pragma unroll
        for (int k = 0; k < 3; k++) {
            const int f   = tid + (k << 8);   // float4-index within patch 0..767
            const int c   = f >> 8;           // channel
            const int rem = f & 255;
            const int r   = rem >> 3;         // row in patch
            const int c4  = rem & 7;          // float4 in row
            const int idx = base4 + c * C_STRIDE4 + r * W4 + c4;
            float4 a = x[idx];
            float4 b = xr[idx];
            acc += fabsf(a.x - b.x) + fabsf(a.y - b.y)
                 + fabsf(a.z - b.z) + fabsf(a.w - b.w);
        }

        #pragma unroll
        for (int o = 16; o > 0; o >>= 1)
            acc += __shfl_down_sync(0xFFFFFFFFu, acc, o);

        if ((tid & 31) == 0) s[tid >> 5] = acc;
        __syncthreads();

        if (tid == 0) {
            float v = s[0];
            #pragma unroll
            for (int q = 1; q < 8; q++) v += s[q];
            const float P = v * (0.5f / 3072.0f);
            atomicMax(&g_M[t], __float_as_int(P));   // valid: P >= 0
        }
        __syncthreads();   // protect s[] before next iteration overwrites
    }

    // CTA done with all its patches -> completion handshake
    if (tid == 0) {
        __threadfence();
        const unsigned int old = atomicAdd(&g_count, 1u);
        last = (old == NCTA - 1);
    }
    __syncthreads();

    if (last) {
        __threadfence();
        if (tid < 32) {
            float v = __int_as_float(__ldcg(&g_M[tid]));
            #pragma unroll
            for (int o = 16; o > 0; o >>= 1)
                v += __shfl_down_sync(0xFFFFFFFFu, v, o);
            if (tid == 0) {
                out[0] = logf(v * (1.0f / 32.0f));
                g_count = 0;               // reset for next graph replay
            }
            g_M[tid] = 0;
        }
    }
}

extern "C" void kernel_launch(void* const* d_in, const int* in_sizes, int n_in,
                              void* d_out, int out_size)
{
    const float4* x  = (const float4*)d_in[0];
    const float4* xr = (const float4*)d_in[1];
    patch_loss_fused<<<NCTA, 256>>>(x, xr, (float*)d_out);
}